// round 1
// baseline (speedup 1.0000x reference)
#include <cuda_runtime.h>
#include <math.h>

// Problem dims
#define B_   64
#define N_   256
#define D_   1024
#define E_   8
#define ET_  4
#define HT_  1024
#define HC_  4096
#define HM_  4096
#define BND  (B_*N_*D_)   // 16777216

// ---------------- device scratch (allocation-free: __device__ globals) ------
__device__ float g_h[BND];                 // 64 MB: modulated LN output / h2
__device__ float g_mix[BND];               // 64 MB: mixer accumulation
__device__ float g_hid[134217728];         // 512 MB: per-(sample,slot) hidden (1M floats each), reused by MLP hid
__device__ float g_mod[B_*6144];           // adaLN modulation (pre-bias; bias added at consumption)
__device__ float g_rin[B_*D_];             // mean-pooled router input
__device__ float g_probs[B_*E_];
__device__ float g_combine[B_*E_];
__device__ int   g_top1[B_];
__device__ unsigned char g_slot[B_*E_];    // 0/1 = which scratch slot, 255 = not selected

// ---------------- math helpers ----------------------------------------------
__device__ __forceinline__ float gelu_f(float x){
    const float c0 = 0.7978845608028654f;   // sqrt(2/pi)
    float x3 = x*x*x;
    float t = tanhf(c0*(x + 0.044715f*x3));
    return 0.5f*x*(1.0f+t);
}
__device__ __forceinline__ float silu_f(float x){
    return x / (1.0f + __expf(-x));
}

// ---------------- GEMM modes -------------------------------------------------
enum { M_TOK1=0, M_TOK2=1, M_CH1=2, M_CH2=3, M_MLP1=4, M_MLP2=5, M_MOD=6 };

// 128x128x8 register-blocked SGEMM, 256 threads, 8x8 per thread.
// Per-mode specialization via if constexpr.
template<int MODE>
__global__ __launch_bounds__(256) void gemm_tpl(
    const float* __restrict__ Aext,   // c for M_MOD, else unused
    const float* __restrict__ W,
    const float* __restrict__ bias,
    const float* __restrict__ b_ada,  // M_MLP2 only
    float* __restrict__ outp)         // d_out for M_MLP2
{
    constexpr int Ntot = (MODE==M_TOK1)?HT_ : (MODE==M_TOK2)?N_
                       : (MODE==M_CH1)?HC_ : (MODE==M_CH2)?D_
                       : (MODE==M_MLP1)?HM_ : (MODE==M_MLP2)?D_ : 6144;
    constexpr int Ktot = (MODE==M_TOK1)?N_ : (MODE==M_CH2||MODE==M_MLP2)?HC_ : D_;
    constexpr int LDA  = (MODE==M_CH2||MODE==M_MLP2)?4096 : 1024;
    constexpr int LDC  = (MODE==M_TOK1)?1024 : (MODE==M_CH1||MODE==M_MLP1)?4096 : 1;
    constexpr bool AKM = (MODE==M_TOK1);  // A is K-major (h transposed view)

    const int tid = threadIdx.x;
    const int m0 = blockIdx.y * 128;
    const int n0 = blockIdx.x * 128;

    const float* Ap = nullptr;
    const float* We = W;
    const float* be = bias;
    float* Cp = nullptr;
    float* mixp = nullptr;
    float wgt = 0.f;
    int kbeg = 0, kend = Ktot;

    if constexpr (MODE==M_TOK1 || MODE==M_TOK2 || MODE==M_CH1 || MODE==M_CH2) {
        int b = blockIdx.z >> 2;
        int e = blockIdx.z & 3;
        int eg = (MODE==M_CH1 || MODE==M_CH2) ? (ET_ + e) : e;
        unsigned char sl = g_slot[b*E_ + eg];
        if (sl == 255u) return;                 // expert not selected for this sample
        float* hid = g_hid + (size_t)(b*2 + sl) * 1048576u;
        if constexpr (MODE==M_TOK1) {
            Ap = g_h + (size_t)b*N_*D_;         // A[m,k] = h[b][k][m]
            We = W   + (size_t)e*N_*HT_;
            be = bias + e*HT_;
            Cp = hid;                           // (1024 x 1024)
        } else if constexpr (MODE==M_TOK2) {
            Ap = hid;                           // (1024 x 1024) row-major
            We = W   + (size_t)e*HT_*N_;
            be = bias + e*N_;
            mixp = g_mix + (size_t)b*N_*D_;
            wgt = g_combine[b*E_ + eg];
        } else if constexpr (MODE==M_CH1) {
            Ap = g_h + (size_t)b*N_*D_;         // (256 x 1024) row-major
            We = W   + (size_t)e*D_*HC_;
            be = bias + e*HC_;
            Cp = hid;                           // (256 x 4096)
        } else {                                 // M_CH2
            Ap = hid;                           // (256 x 4096) row-major
            We = W   + (size_t)e*HC_*D_;
            be = bias + e*D_;
            mixp = g_mix + (size_t)b*N_*D_;
            wgt = g_combine[b*E_ + eg];
        }
    } else if constexpr (MODE==M_MLP1) {
        Ap = g_h;                                // (16384 x 1024)
        Cp = g_hid;                              // (16384 x 4096)
    } else if constexpr (MODE==M_MLP2) {
        Ap = g_hid;                              // (16384 x 4096)
    } else {                                     // M_MOD: K-split slice
        Ap = Aext;                               // c (64 x 1024), silu applied on load
        kbeg = blockIdx.z * 128;
        kend = kbeg + 128;
    }

    __shared__ __align__(16) float As[8][132];
    __shared__ __align__(16) float Bs[8][132];

    float acc[8][8];
    #pragma unroll
    for (int i=0;i<8;i++)
        #pragma unroll
        for (int j=0;j<8;j++) acc[i][j] = 0.f;

    const int tx = tid & 15, ty = tid >> 4;

    for (int k0 = kbeg; k0 < kend; k0 += 8) {
        // ---- load A tile into As[k][m] ----
        #pragma unroll
        for (int j=0;j<4;j++){
            int i = tid + j*256;
            if constexpr (AKM) {
                int m = i & 127, kk = i >> 7;
                As[kk][m] = Ap[(size_t)(k0+kk)*D_ + (m0+m)];
            } else {
                int m = i >> 3, kk = i & 7;
                float v;
                if constexpr (MODE==M_MOD) {
                    int gm = m0 + m;
                    v = (gm < B_) ? silu_f(Ap[gm*D_ + (k0+kk)]) : 0.f;
                } else {
                    v = Ap[(size_t)(m0+m)*LDA + (k0+kk)];
                }
                As[kk][m] = v;
            }
        }
        // ---- load B tile (row-major K x Ntot) ----
        #pragma unroll
        for (int j=0;j<4;j++){
            int i = tid + j*256;
            int kk = i >> 7, n = i & 127;
            Bs[kk][n] = We[(size_t)(k0+kk)*Ntot + (n0+n)];
        }
        __syncthreads();
        #pragma unroll
        for (int kk=0; kk<8; kk++){
            float4 a0 = *reinterpret_cast<const float4*>(&As[kk][ty*8]);
            float4 a1 = *reinterpret_cast<const float4*>(&As[kk][ty*8+4]);
            float4 b0 = *reinterpret_cast<const float4*>(&Bs[kk][tx*8]);
            float4 b1 = *reinterpret_cast<const float4*>(&Bs[kk][tx*8+4]);
            float a[8] = {a0.x,a0.y,a0.z,a0.w,a1.x,a1.y,a1.z,a1.w};
            float bb[8]= {b0.x,b0.y,b0.z,b0.w,b1.x,b1.y,b1.z,b1.w};
            #pragma unroll
            for (int i=0;i<8;i++)
                #pragma unroll
                for (int j=0;j<8;j++)
                    acc[i][j] = fmaf(a[i], bb[j], acc[i][j]);
        }
        __syncthreads();
    }

    // ---- epilogue ----
    #pragma unroll
    for (int i=0;i<8;i++){
        int m = m0 + ty*8 + i;
        #pragma unroll
        for (int j=0;j<8;j++){
            int n = n0 + tx*8 + j;
            float v = acc[i][j];
            if constexpr (MODE==M_TOK1 || MODE==M_CH1 || MODE==M_MLP1) {
                Cp[(size_t)m*LDC + n] = gelu_f(v + be[n]);
            } else if constexpr (MODE==M_TOK2) {
                // C[m=d][n=token] -> mix[b][token][d]
                atomicAdd(&mixp[(size_t)n*D_ + m], wgt*(v + be[n]));
            } else if constexpr (MODE==M_CH2) {
                atomicAdd(&mixp[(size_t)m*D_ + n], wgt*(v + be[n]));
            } else if constexpr (MODE==M_MLP2) {
                int b = m >> 8;
                float gml = g_mod[b*6144 + 5*D_ + n] + b_ada[5*D_ + n];
                size_t o = (size_t)m*D_ + n;
                outp[o] = outp[o] + gml*(v + be[n]);   // x1 (staged in d_out) + g_mlp * mlp_out
            } else { // M_MOD (K-split partial)
                if (m < B_) atomicAdd(&g_mod[m*6144 + n], v);
            }
        }
    }
}

// ---------------- elementwise / routing kernels ------------------------------

__global__ void zero_mod_kernel(){
    int i = blockIdx.x*1024 + threadIdx.x;   // exactly 384*1024 = 64*6144
    g_mod[i] = 0.f;
}

// h = modulate(ln(x), s_msa, sc_msa); mix = 0
__global__ void ew1_kernel(const float* __restrict__ x, const float* __restrict__ b_ada){
    int r = blockIdx.x;            // b*256 + n
    int b = r >> 8;
    int tid = threadIdx.x;
    const float* xr = x + (size_t)r*D_;
    float v[4];
    #pragma unroll
    for (int k=0;k<4;k++) v[k] = xr[tid*4+k];
    float s = v[0]+v[1]+v[2]+v[3];
    float q = v[0]*v[0]+v[1]*v[1]+v[2]*v[2]+v[3]*v[3];
    __shared__ float rs[256], rq[256];
    rs[tid]=s; rq[tid]=q; __syncthreads();
    for (int st=128; st>0; st>>=1){
        if (tid<st){ rs[tid]+=rs[tid+st]; rq[tid]+=rq[tid+st]; }
        __syncthreads();
    }
    float mu  = rs[0]*(1.f/1024.f);
    float var = rq[0]*(1.f/1024.f) - mu*mu;
    float rstd = rsqrtf(var + 1e-6f);
    #pragma unroll
    for (int k=0;k<4;k++){
        int d = tid*4+k;
        float sft = g_mod[b*6144 + d]        + b_ada[d];
        float scl = g_mod[b*6144 + D_ + d]   + b_ada[D_ + d];
        float y = (v[k]-mu)*rstd;
        g_h  [(size_t)r*D_ + d] = y*(1.f+scl) + sft;
        g_mix[(size_t)r*D_ + d] = 0.f;
    }
}

// r_in[b][d] = mean_n h[b][n][d]
__global__ void rin_kernel(){
    int b = blockIdx.y;
    int d = blockIdx.x*256 + threadIdx.x;
    const float* hb = g_h + (size_t)b*N_*D_;
    float s = 0.f;
    for (int n=0;n<N_;n++) s += hb[(size_t)n*D_ + d];
    g_rin[b*D_ + d] = s * (1.f/256.f);
}

__global__ void route_kernel(const float* __restrict__ wr){
    int b = blockIdx.x, tid = threadIdx.x;
    float acc[E_] = {0,0,0,0,0,0,0,0};
    for (int d=tid; d<D_; d+=256){
        float v = g_rin[b*D_ + d];
        #pragma unroll
        for (int e=0;e<E_;e++) acc[e] = fmaf(v, wr[d*E_ + e], acc[e]);
    }
    __shared__ float red[256];
    __shared__ float slog[E_];
    for (int e=0;e<E_;e++){
        red[tid] = acc[e];
        __syncthreads();
        for (int st=128; st>0; st>>=1){
            if (tid<st) red[tid] += red[tid+st];
            __syncthreads();
        }
        if (tid==0) slog[e] = red[0];
        __syncthreads();
    }
    if (tid==0){
        float p[E_];
        float mx = slog[0];
        for (int e=1;e<E_;e++) mx = fmaxf(mx, slog[e]);
        float ssum = 0.f;
        for (int e=0;e<E_;e++){ p[e] = expf(slog[e]-mx); ssum += p[e]; }
        for (int e=0;e<E_;e++){ p[e] /= ssum; g_probs[b*E_+e] = p[e]; }
        int i0 = 0;
        for (int e=1;e<E_;e++) if (p[e] > p[i0]) i0 = e;
        int i1 = (i0==0) ? 1 : 0;
        for (int e=0;e<E_;e++) if (e!=i0 && p[e] > p[i1]) i1 = e;
        float t = p[i0] + p[i1];
        for (int e=0;e<E_;e++){ g_combine[b*E_+e] = 0.f; g_slot[b*E_+e] = 255u; }
        g_combine[b*E_+i0] = p[i0]/t;  g_slot[b*E_+i0] = 0u;
        g_combine[b*E_+i1] = p[i1]/t;  g_slot[b*E_+i1] = 1u;
        g_top1[b] = i0;
    }
}

__global__ void aux_kernel(float* __restrict__ outp, int out_size){
    if (threadIdx.x != 0) return;
    float meanp[E_]; int cnt[E_];
    for (int e=0;e<E_;e++){ meanp[e]=0.f; cnt[e]=0; }
    for (int b=0;b<B_;b++){
        for (int e=0;e<E_;e++) meanp[e] += g_probs[b*E_+e];
        cnt[g_top1[b]]++;
    }
    float aux = 0.f;
    for (int e=0;e<E_;e++) aux += (meanp[e]*(1.f/B_)) * ((float)cnt[e]*(1.f/B_));
    aux *= (float)E_;
    if (out_size > BND) outp[BND] = aux;
}

// x1 = x + g_msa*mix (staged to d_out); h2 = modulate(ln(x1), s_mlp, sc_mlp) -> g_h
__global__ void ew2_kernel(const float* __restrict__ x, const float* __restrict__ b_ada,
                           float* __restrict__ outp){
    int r = blockIdx.x;
    int b = r >> 8;
    int tid = threadIdx.x;
    float v[4];
    #pragma unroll
    for (int k=0;k<4;k++){
        int d = tid*4+k;
        float g = g_mod[b*6144 + 2*D_ + d] + b_ada[2*D_ + d];
        float x1 = x[(size_t)r*D_ + d] + g * g_mix[(size_t)r*D_ + d];
        outp[(size_t)r*D_ + d] = x1;
        v[k] = x1;
    }
    float s = v[0]+v[1]+v[2]+v[3];
    float q = v[0]*v[0]+v[1]*v[1]+v[2]*v[2]+v[3]*v[3];
    __shared__ float rs[256], rq[256];
    rs[tid]=s; rq[tid]=q; __syncthreads();
    for (int st=128; st>0; st>>=1){
        if (tid<st){ rs[tid]+=rs[tid+st]; rq[tid]+=rq[tid+st]; }
        __syncthreads();
    }
    float mu  = rs[0]*(1.f/1024.f);
    float var = rq[0]*(1.f/1024.f) - mu*mu;
    float rstd = rsqrtf(var + 1e-6f);
    #pragma unroll
    for (int k=0;k<4;k++){
        int d = tid*4+k;
        float sft = g_mod[b*6144 + 3*D_ + d] + b_ada[3*D_ + d];
        float scl = g_mod[b*6144 + 4*D_ + d] + b_ada[4*D_ + d];
        float y = (v[k]-mu)*rstd;
        g_h[(size_t)r*D_ + d] = y*(1.f+scl) + sft;
    }
}

// ---------------- launch ------------------------------------------------------
extern "C" void kernel_launch(void* const* d_in, const int* in_sizes, int n_in,
                              void* d_out, int out_size) {
    const float* x        = (const float*)d_in[0];
    const float* c        = (const float*)d_in[1];
    const float* w_ada    = (const float*)d_in[2];
    const float* b_ada    = (const float*)d_in[3];
    const float* w_router = (const float*)d_in[4];
    const float* tm_w1    = (const float*)d_in[5];
    const float* tm_b1    = (const float*)d_in[6];
    const float* tm_w2    = (const float*)d_in[7];
    const float* tm_b2    = (const float*)d_in[8];
    const float* cm_w1    = (const float*)d_in[9];
    const float* cm_b1    = (const float*)d_in[10];
    const float* cm_w2    = (const float*)d_in[11];
    const float* cm_b2    = (const float*)d_in[12];
    const float* mlp_w1   = (const float*)d_in[13];
    const float* mlp_b1   = (const float*)d_in[14];
    const float* mlp_w2   = (const float*)d_in[15];
    const float* mlp_b2   = (const float*)d_in[16];
    float* outp = (float*)d_out;

    // adaLN modulation (K-split, atomic into zeroed g_mod; bias folded at consumers)
    zero_mod_kernel<<<384, 1024>>>();
    gemm_tpl<M_MOD><<<dim3(48,1,8), 256>>>(c, w_ada, nullptr, nullptr, nullptr);

    // LN + modulate; zero mix
    ew1_kernel<<<B_*N_, 256>>>(x, b_ada);

    // routing
    rin_kernel<<<dim3(4, B_), 256>>>();
    route_kernel<<<B_, 256>>>(w_router);
    aux_kernel<<<1, 32>>>(outp, out_size);

    // routed experts (gated per (sample, expert); non-selected blocks exit immediately)
    gemm_tpl<M_TOK1><<<dim3( 8, 8, B_*4), 256>>>(nullptr, tm_w1, tm_b1, nullptr, nullptr);
    gemm_tpl<M_CH1> <<<dim3(32, 2, B_*4), 256>>>(nullptr, cm_w1, cm_b1, nullptr, nullptr);
    gemm_tpl<M_TOK2><<<dim3( 2, 8, B_*4), 256>>>(nullptr, tm_w2, tm_b2, nullptr, nullptr);
    gemm_tpl<M_CH2> <<<dim3( 8, 2, B_*4), 256>>>(nullptr, cm_w2, cm_b2, nullptr, nullptr);

    // residual + second LN/modulate (x1 staged in d_out)
    ew2_kernel<<<B_*N_, 256>>>(x, b_ada, outp);

    // dense MLP, second residual fused into MLP2 epilogue
    gemm_tpl<M_MLP1><<<dim3(32, 128, 1), 256>>>(nullptr, mlp_w1, mlp_b1, nullptr, nullptr);
    gemm_tpl<M_MLP2><<<dim3( 8, 128, 1), 256>>>(nullptr, mlp_w2, mlp_b2, b_ada, outp);
}

// round 2
// speedup vs baseline: 1.0015x; 1.0015x over previous
#include <cuda_runtime.h>
#include <math.h>

// Problem dims
#define B_   64
#define N_   256
#define D_   1024
#define E_   8
#define ET_  4
#define HT_  1024
#define HC_  4096
#define HM_  4096
#define BND  (B_*N_*D_)   // 16777216

// ---------------- device scratch (allocation-free: __device__ globals) ------
__device__ float g_h[BND];                 // 64 MB: modulated LN output / h2
__device__ float g_mix[BND];               // 64 MB: mixer accumulation
__device__ float g_hid[134217728];         // 512 MB: per-(sample,slot) hidden (1M floats each), reused by MLP hid
__device__ float g_mod[B_*6144];           // adaLN modulation (pre-bias; bias added at consumption)
__device__ float g_rin[B_*D_];             // mean-pooled router input
__device__ float g_probs[B_*E_];
__device__ float g_combine[B_*E_];
__device__ int   g_top1[B_];
__device__ unsigned char g_slot[B_*E_];    // 0/1 = which scratch slot, 255 = not selected

// ---------------- math helpers ----------------------------------------------
__device__ __forceinline__ float gelu_f(float x){
    const float c0 = 0.7978845608028654f;   // sqrt(2/pi)
    float x3 = x*x*x;
    float t = tanhf(c0*(x + 0.044715f*x3));
    return 0.5f*x*(1.0f+t);
}
__device__ __forceinline__ float silu_f(float x){
    return x / (1.0f + __expf(-x));
}

// ---------------- GEMM modes -------------------------------------------------
enum { M_TOK1=0, M_TOK2=1, M_CH1=2, M_CH2=3, M_MLP1=4, M_MLP2=5, M_MOD=6 };

// 128x128x8 register-blocked SGEMM, 256 threads, 8x8 per thread.
// Per-mode specialization via if constexpr.
template<int MODE>
__global__ __launch_bounds__(256) void gemm_tpl(
    const float* __restrict__ Aext,   // c for M_MOD, else unused
    const float* __restrict__ W,
    const float* __restrict__ bias,
    const float* __restrict__ b_ada,  // M_MLP2 only
    float* __restrict__ outp)         // d_out for M_MLP2
{
    constexpr int Ntot = (MODE==M_TOK1)?HT_ : (MODE==M_TOK2)?N_
                       : (MODE==M_CH1)?HC_ : (MODE==M_CH2)?D_
                       : (MODE==M_MLP1)?HM_ : (MODE==M_MLP2)?D_ : 6144;
    constexpr int Ktot = (MODE==M_TOK1)?N_ : (MODE==M_CH2||MODE==M_MLP2)?HC_ : D_;
    constexpr int LDA  = (MODE==M_CH2||MODE==M_MLP2)?4096 : 1024;
    constexpr int LDC  = (MODE==M_TOK1)?1024 : (MODE==M_CH1||MODE==M_MLP1)?4096 : 1;
    constexpr bool AKM = (MODE==M_TOK1);  // A is K-major (h transposed view)

    const int tid = threadIdx.x;
    const int m0 = blockIdx.y * 128;
    const int n0 = blockIdx.x * 128;

    const float* Ap = nullptr;
    const float* We = W;
    const float* be = bias;
    float* Cp = nullptr;
    float* mixp = nullptr;
    float wgt = 0.f;
    int kbeg = 0, kend = Ktot;

    if constexpr (MODE==M_TOK1 || MODE==M_TOK2 || MODE==M_CH1 || MODE==M_CH2) {
        int b = blockIdx.z >> 2;
        int e = blockIdx.z & 3;
        int eg = (MODE==M_CH1 || MODE==M_CH2) ? (ET_ + e) : e;
        unsigned char sl = g_slot[b*E_ + eg];
        if (sl == 255u) return;                 // expert not selected for this sample
        float* hid = g_hid + (size_t)(b*2 + sl) * 1048576u;
        if constexpr (MODE==M_TOK1) {
            Ap = g_h + (size_t)b*N_*D_;         // A[m,k] = h[b][k][m]
            We = W   + (size_t)e*N_*HT_;
            be = bias + e*HT_;
            Cp = hid;                           // (1024 x 1024)
        } else if constexpr (MODE==M_TOK2) {
            Ap = hid;                           // (1024 x 1024) row-major
            We = W   + (size_t)e*HT_*N_;
            be = bias + e*N_;
            mixp = g_mix + (size_t)b*N_*D_;
            wgt = g_combine[b*E_ + eg];
        } else if constexpr (MODE==M_CH1) {
            Ap = g_h + (size_t)b*N_*D_;         // (256 x 1024) row-major
            We = W   + (size_t)e*D_*HC_;
            be = bias + e*HC_;
            Cp = hid;                           // (256 x 4096)
        } else {                                 // M_CH2
            Ap = hid;                           // (256 x 4096) row-major
            We = W   + (size_t)e*HC_*D_;
            be = bias + e*D_;
            mixp = g_mix + (size_t)b*N_*D_;
            wgt = g_combine[b*E_ + eg];
        }
    } else if constexpr (MODE==M_MLP1) {
        Ap = g_h;                                // (16384 x 1024)
        Cp = g_hid;                              // (16384 x 4096)
    } else if constexpr (MODE==M_MLP2) {
        Ap = g_hid;                              // (16384 x 4096)
    } else {                                     // M_MOD: K-split slice
        Ap = Aext;                               // c (64 x 1024), silu applied on load
        kbeg = blockIdx.z * 128;
        kend = kbeg + 128;
    }

    __shared__ __align__(16) float As[8][132];
    __shared__ __align__(16) float Bs[8][132];

    float acc[8][8];
    #pragma unroll
    for (int i=0;i<8;i++)
        #pragma unroll
        for (int j=0;j<8;j++) acc[i][j] = 0.f;

    const int tx = tid & 15, ty = tid >> 4;

    for (int k0 = kbeg; k0 < kend; k0 += 8) {
        // ---- load A tile into As[k][m] ----
        #pragma unroll
        for (int j=0;j<4;j++){
            int i = tid + j*256;
            if constexpr (AKM) {
                int m = i & 127, kk = i >> 7;
                As[kk][m] = Ap[(size_t)(k0+kk)*D_ + (m0+m)];
            } else {
                int m = i >> 3, kk = i & 7;
                float v;
                if constexpr (MODE==M_MOD) {
                    int gm = m0 + m;
                    v = (gm < B_) ? silu_f(Ap[gm*D_ + (k0+kk)]) : 0.f;
                } else {
                    v = Ap[(size_t)(m0+m)*LDA + (k0+kk)];
                }
                As[kk][m] = v;
            }
        }
        // ---- load B tile (row-major K x Ntot) ----
        #pragma unroll
        for (int j=0;j<4;j++){
            int i = tid + j*256;
            int kk = i >> 7, n = i & 127;
            Bs[kk][n] = We[(size_t)(k0+kk)*Ntot + (n0+n)];
        }
        __syncthreads();
        #pragma unroll
        for (int kk=0; kk<8; kk++){
            float4 a0 = *reinterpret_cast<const float4*>(&As[kk][ty*8]);
            float4 a1 = *reinterpret_cast<const float4*>(&As[kk][ty*8+4]);
            float4 b0 = *reinterpret_cast<const float4*>(&Bs[kk][tx*8]);
            float4 b1 = *reinterpret_cast<const float4*>(&Bs[kk][tx*8+4]);
            float a[8] = {a0.x,a0.y,a0.z,a0.w,a1.x,a1.y,a1.z,a1.w};
            float bb[8]= {b0.x,b0.y,b0.z,b0.w,b1.x,b1.y,b1.z,b1.w};
            #pragma unroll
            for (int i=0;i<8;i++)
                #pragma unroll
                for (int j=0;j<8;j++)
                    acc[i][j] = fmaf(a[i], bb[j], acc[i][j]);
        }
        __syncthreads();
    }

    // ---- epilogue ----
    #pragma unroll
    for (int i=0;i<8;i++){
        int m = m0 + ty*8 + i;
        #pragma unroll
        for (int j=0;j<8;j++){
            int n = n0 + tx*8 + j;
            float v = acc[i][j];
            if constexpr (MODE==M_TOK1 || MODE==M_CH1 || MODE==M_MLP1) {
                Cp[(size_t)m*LDC + n] = gelu_f(v + be[n]);
            } else if constexpr (MODE==M_TOK2) {
                // C[m=d][n=token] -> mix[b][token][d]
                atomicAdd(&mixp[(size_t)n*D_ + m], wgt*(v + be[n]));
            } else if constexpr (MODE==M_CH2) {
                atomicAdd(&mixp[(size_t)m*D_ + n], wgt*(v + be[n]));
            } else if constexpr (MODE==M_MLP2) {
                int b = m >> 8;
                float gml = g_mod[b*6144 + 5*D_ + n] + b_ada[5*D_ + n];
                size_t o = (size_t)m*D_ + n;
                outp[o] = outp[o] + gml*(v + be[n]);   // x1 (staged in d_out) + g_mlp * mlp_out
            } else { // M_MOD (K-split partial)
                if (m < B_) atomicAdd(&g_mod[m*6144 + n], v);
            }
        }
    }
}

// ---------------- elementwise / routing kernels ------------------------------

__global__ void zero_mod_kernel(){
    int i = blockIdx.x*1024 + threadIdx.x;   // exactly 384*1024 = 64*6144
    g_mod[i] = 0.f;
}

// h = modulate(ln(x), s_msa, sc_msa); mix = 0
__global__ void ew1_kernel(const float* __restrict__ x, const float* __restrict__ b_ada){
    int r = blockIdx.x;            // b*256 + n
    int b = r >> 8;
    int tid = threadIdx.x;
    const float* xr = x + (size_t)r*D_;
    float v[4];
    #pragma unroll
    for (int k=0;k<4;k++) v[k] = xr[tid*4+k];
    float s = v[0]+v[1]+v[2]+v[3];
    float q = v[0]*v[0]+v[1]*v[1]+v[2]*v[2]+v[3]*v[3];
    __shared__ float rs[256], rq[256];
    rs[tid]=s; rq[tid]=q; __syncthreads();
    for (int st=128; st>0; st>>=1){
        if (tid<st){ rs[tid]+=rs[tid+st]; rq[tid]+=rq[tid+st]; }
        __syncthreads();
    }
    float mu  = rs[0]*(1.f/1024.f);
    float var = rq[0]*(1.f/1024.f) - mu*mu;
    float rstd = rsqrtf(var + 1e-6f);
    #pragma unroll
    for (int k=0;k<4;k++){
        int d = tid*4+k;
        float sft = g_mod[b*6144 + d]        + b_ada[d];
        float scl = g_mod[b*6144 + D_ + d]   + b_ada[D_ + d];
        float y = (v[k]-mu)*rstd;
        g_h  [(size_t)r*D_ + d] = y*(1.f+scl) + sft;
        g_mix[(size_t)r*D_ + d] = 0.f;
    }
}

// r_in[b][d] = mean_n h[b][n][d]
__global__ void rin_kernel(){
    int b = blockIdx.y;
    int d = blockIdx.x*256 + threadIdx.x;
    const float* hb = g_h + (size_t)b*N_*D_;
    float s = 0.f;
    for (int n=0;n<N_;n++) s += hb[(size_t)n*D_ + d];
    g_rin[b*D_ + d] = s * (1.f/256.f);
}

__global__ void route_kernel(const float* __restrict__ wr){
    int b = blockIdx.x, tid = threadIdx.x;
    float acc[E_] = {0,0,0,0,0,0,0,0};
    for (int d=tid; d<D_; d+=256){
        float v = g_rin[b*D_ + d];
        #pragma unroll
        for (int e=0;e<E_;e++) acc[e] = fmaf(v, wr[d*E_ + e], acc[e]);
    }
    __shared__ float red[256];
    __shared__ float slog[E_];
    for (int e=0;e<E_;e++){
        red[tid] = acc[e];
        __syncthreads();
        for (int st=128; st>0; st>>=1){
            if (tid<st) red[tid] += red[tid+st];
            __syncthreads();
        }
        if (tid==0) slog[e] = red[0];
        __syncthreads();
    }
    if (tid==0){
        float p[E_];
        float mx = slog[0];
        for (int e=1;e<E_;e++) mx = fmaxf(mx, slog[e]);
        float ssum = 0.f;
        for (int e=0;e<E_;e++){ p[e] = expf(slog[e]-mx); ssum += p[e]; }
        for (int e=0;e<E_;e++){ p[e] /= ssum; g_probs[b*E_+e] = p[e]; }
        int i0 = 0;
        for (int e=1;e<E_;e++) if (p[e] > p[i0]) i0 = e;
        int i1 = (i0==0) ? 1 : 0;
        for (int e=0;e<E_;e++) if (e!=i0 && p[e] > p[i1]) i1 = e;
        float t = p[i0] + p[i1];
        for (int e=0;e<E_;e++){ g_combine[b*E_+e] = 0.f; g_slot[b*E_+e] = 255u; }
        g_combine[b*E_+i0] = p[i0]/t;  g_slot[b*E_+i0] = 0u;
        g_combine[b*E_+i1] = p[i1]/t;  g_slot[b*E_+i1] = 1u;
        g_top1[b] = i0;
    }
}

__global__ void aux_kernel(float* __restrict__ outp, int out_size){
    if (threadIdx.x != 0) return;
    float meanp[E_]; int cnt[E_];
    for (int e=0;e<E_;e++){ meanp[e]=0.f; cnt[e]=0; }
    for (int b=0;b<B_;b++){
        for (int e=0;e<E_;e++) meanp[e] += g_probs[b*E_+e];
        cnt[g_top1[b]]++;
    }
    float aux = 0.f;
    for (int e=0;e<E_;e++) aux += (meanp[e]*(1.f/B_)) * ((float)cnt[e]*(1.f/B_));
    aux *= (float)E_;
    if (out_size > BND) outp[BND] = aux;
}

// x1 = x + g_msa*mix (staged to d_out); h2 = modulate(ln(x1), s_mlp, sc_mlp) -> g_h
__global__ void ew2_kernel(const float* __restrict__ x, const float* __restrict__ b_ada,
                           float* __restrict__ outp){
    int r = blockIdx.x;
    int b = r >> 8;
    int tid = threadIdx.x;
    float v[4];
    #pragma unroll
    for (int k=0;k<4;k++){
        int d = tid*4+k;
        float g = g_mod[b*6144 + 2*D_ + d] + b_ada[2*D_ + d];
        float x1 = x[(size_t)r*D_ + d] + g * g_mix[(size_t)r*D_ + d];
        outp[(size_t)r*D_ + d] = x1;
        v[k] = x1;
    }
    float s = v[0]+v[1]+v[2]+v[3];
    float q = v[0]*v[0]+v[1]*v[1]+v[2]*v[2]+v[3]*v[3];
    __shared__ float rs[256], rq[256];
    rs[tid]=s; rq[tid]=q; __syncthreads();
    for (int st=128; st>0; st>>=1){
        if (tid<st){ rs[tid]+=rs[tid+st]; rq[tid]+=rq[tid+st]; }
        __syncthreads();
    }
    float mu  = rs[0]*(1.f/1024.f);
    float var = rq[0]*(1.f/1024.f) - mu*mu;
    float rstd = rsqrtf(var + 1e-6f);
    #pragma unroll
    for (int k=0;k<4;k++){
        int d = tid*4+k;
        float sft = g_mod[b*6144 + 3*D_ + d] + b_ada[3*D_ + d];
        float scl = g_mod[b*6144 + 4*D_ + d] + b_ada[4*D_ + d];
        float y = (v[k]-mu)*rstd;
        g_h[(size_t)r*D_ + d] = y*(1.f+scl) + sft;
    }
}

// ---------------- launch ------------------------------------------------------
extern "C" void kernel_launch(void* const* d_in, const int* in_sizes, int n_in,
                              void* d_out, int out_size) {
    const float* x        = (const float*)d_in[0];
    const float* c        = (const float*)d_in[1];
    const float* w_ada    = (const float*)d_in[2];
    const float* b_ada    = (const float*)d_in[3];
    const float* w_router = (const float*)d_in[4];
    const float* tm_w1    = (const float*)d_in[5];
    const float* tm_b1    = (const float*)d_in[6];
    const float* tm_w2    = (const float*)d_in[7];
    const float* tm_b2    = (const float*)d_in[8];
    const float* cm_w1    = (const float*)d_in[9];
    const float* cm_b1    = (const float*)d_in[10];
    const float* cm_w2    = (const float*)d_in[11];
    const float* cm_b2    = (const float*)d_in[12];
    const float* mlp_w1   = (const float*)d_in[13];
    const float* mlp_b1   = (const float*)d_in[14];
    const float* mlp_w2   = (const float*)d_in[15];
    const float* mlp_b2   = (const float*)d_in[16];
    float* outp = (float*)d_out;

    // adaLN modulation (K-split, atomic into zeroed g_mod; bias folded at consumers)
    zero_mod_kernel<<<384, 1024>>>();
    gemm_tpl<M_MOD><<<dim3(48,1,8), 256>>>(c, w_ada, nullptr, nullptr, nullptr);

    // LN + modulate; zero mix
    ew1_kernel<<<B_*N_, 256>>>(x, b_ada);

    // routing
    rin_kernel<<<dim3(4, B_), 256>>>();
    route_kernel<<<B_, 256>>>(w_router);
    aux_kernel<<<1, 32>>>(outp, out_size);

    // routed experts (gated per (sample, expert); non-selected blocks exit immediately)
    gemm_tpl<M_TOK1><<<dim3( 8, 8, B_*4), 256>>>(nullptr, tm_w1, tm_b1, nullptr, nullptr);
    gemm_tpl<M_CH1> <<<dim3(32, 2, B_*4), 256>>>(nullptr, cm_w1, cm_b1, nullptr, nullptr);
    gemm_tpl<M_TOK2><<<dim3( 2, 8, B_*4), 256>>>(nullptr, tm_w2, tm_b2, nullptr, nullptr);
    gemm_tpl<M_CH2> <<<dim3( 8, 2, B_*4), 256>>>(nullptr, cm_w2, cm_b2, nullptr, nullptr);

    // residual + second LN/modulate (x1 staged in d_out)
    ew2_kernel<<<B_*N_, 256>>>(x, b_ada, outp);

    // dense MLP, second residual fused into MLP2 epilogue
    gemm_tpl<M_MLP1><<<dim3(32, 128, 1), 256>>>(nullptr, mlp_w1, mlp_b1, nullptr, nullptr);
    gemm_tpl<M_MLP2><<<dim3( 8, 128, 1), 256>>>(nullptr, mlp_w2, mlp_b2, b_ada, outp);
}